// round 5
// baseline (speedup 1.0000x reference)
#include <cuda_runtime.h>
#include <math.h>

#define T_TOK 1024
#define E_EXP 16
#define K_TOP 4
#define H_DIM 2048
#define I_DIM 2048
#define CAP   512
#define N1    (2*I_DIM)   /* 4096 */

// ---------------- scratch (device globals; no runtime allocation) ----------------
__device__ int   g_w1p[E_EXP*(H_DIM/4)*N1];     // 33,554,432 int (128MB): [E][H/4][2I], 4 k-values packed per int
__device__ int   g_w2p[E_EXP*(I_DIM/4)*H_DIM];  // 16,777,216 int (64MB):  [E][I/4][H]
__device__ int   g_xq[T_TOK*(H_DIM/4)];         // packed int8 tokens
__device__ float g_xs[T_TOK];
__device__ int   g_topk_i[T_TOK*K_TOP];
__device__ float g_topk_w[T_TOK*K_TOP];
__device__ int   g_rowsrc[E_EXP*CAP];           // source token per dispatch slot, -1 = empty
__device__ int   g_slot[T_TOK*K_TOP];           // dispatch slot per (token,k), -1 = dropped
__device__ int   g_cnt[E_EXP];
__device__ float g_act[E_EXP*CAP*I_DIM];        // 64MB swiglu output
__device__ int   g_hq[E_EXP*CAP*(I_DIM/4)];     // 16MB requantized act
__device__ float g_hs[E_EXP*CAP];
__device__ float g_z[E_EXP*CAP*H_DIM];          // 64MB GEMM2 output

// ---------------- helpers ----------------
__device__ __forceinline__ int packb(float a, float b, float c, float d) {
    return ( __float2int_rn(a) & 0xff)
         | ((__float2int_rn(b) & 0xff) << 8)
         | ((__float2int_rn(c) & 0xff) << 16)
         | ((__float2int_rn(d) & 0xff) << 24);
}
__device__ __forceinline__ int q8c(float v, float s) {
    int q = __float2int_rn(v / s);
    q = max(-127, min(127, q));
    return q & 0xff;
}

// ---------------- weight repack: f32 (int values) -> K-packed int8 ----------------
// in: [E][Kd][Nd] f32; out: [E][Kd/4][Nd] int32 (byte j = k=4*k4+j)
__global__ void k_pack(const float* __restrict__ in, int which, int Kd, int Nd) {
    int* __restrict__ out = which ? g_w2p : g_w1p;
    long long i4  = (long long)blockIdx.x * blockDim.x + threadIdx.x;
    long long lin = i4 * 4;
    long long perE = (long long)(Kd >> 2) * Nd;
    int e  = (int)(lin / perE);
    long long rem = lin - (long long)e * perE;
    int k4 = (int)(rem / Nd);
    int n  = (int)(rem - (long long)k4 * Nd);
    const float* p = in + ((long long)e * Kd + 4 * k4) * Nd + n;
    float4 r0 = *(const float4*)(p);
    float4 r1 = *(const float4*)(p + Nd);
    float4 r2 = *(const float4*)(p + 2 * Nd);
    float4 r3 = *(const float4*)(p + 3 * Nd);
    int4 o;
    o.x = packb(r0.x, r1.x, r2.x, r3.x);
    o.y = packb(r0.y, r1.y, r2.y, r3.y);
    o.z = packb(r0.z, r1.z, r2.z, r3.z);
    o.w = packb(r0.w, r1.w, r2.w, r3.w);
    *(int4*)(out + lin) = o;
}

// ---------------- gating: softmax + top-4 + renormalize (1 warp / token) ----------------
__global__ void k_gate(const float* __restrict__ logits) {
    int t = blockIdx.x, lane = threadIdx.x;
    float v = (lane < E_EXP) ? logits[t * E_EXP + lane] : -1e30f;
    float m = v;
    #pragma unroll
    for (int o = 16; o; o >>= 1) m = fmaxf(m, __shfl_xor_sync(0xffffffffu, m, o));
    float cur = (lane < E_EXP) ? expf(v - m) : -1.0f;
    float w[K_TOP]; int id[K_TOP];
    #pragma unroll
    for (int k = 0; k < K_TOP; k++) {
        float bv = cur; int bi = lane;
        #pragma unroll
        for (int o = 16; o; o >>= 1) {
            float ov = __shfl_xor_sync(0xffffffffu, bv, o);
            int   oi = __shfl_xor_sync(0xffffffffu, bi, o);
            if (ov > bv || (ov == bv && oi < bi)) { bv = ov; bi = oi; }
        }
        w[k] = bv; id[k] = bi;
        if (lane == bi) cur = -1.0f;
    }
    float s = w[0] + w[1] + w[2] + w[3];
    if (lane < K_TOP) {
        g_topk_i[t * K_TOP + lane] = id[lane];
        g_topk_w[t * K_TOP + lane] = w[lane] / s;
    }
}

// ---------------- per-row dynamic int8 quant (which=0: hidden->xq, 1: act->hq) ----------------
__global__ void k_quant(const float* __restrict__ xin, int which) {
    const float* x; int* q; float* s;
    if (which == 0) { x = xin;  q = g_xq; s = g_xs; }
    else            { x = g_act; q = g_hq; s = g_hs; }
    int r = blockIdx.x, t = threadIdx.x;
    const float* row = x + (long long)r * 2048;
    float4 a = *(const float4*)(row + t * 8);
    float4 b = *(const float4*)(row + t * 8 + 4);
    float mx = fmaxf(fmaxf(fmaxf(fabsf(a.x), fabsf(a.y)), fmaxf(fabsf(a.z), fabsf(a.w))),
                     fmaxf(fmaxf(fabsf(b.x), fabsf(b.y)), fmaxf(fabsf(b.z), fabsf(b.w))));
    __shared__ float sm[256];
    sm[t] = mx; __syncthreads();
    #pragma unroll
    for (int o = 128; o; o >>= 1) { if (t < o) sm[t] = fmaxf(sm[t], sm[t + o]); __syncthreads(); }
    float scale = fmaxf(sm[0] / 127.0f, 1e-8f);
    int2 o2;
    o2.x = q8c(a.x, scale) | (q8c(a.y, scale) << 8) | (q8c(a.z, scale) << 16) | (q8c(a.w, scale) << 24);
    o2.y = q8c(b.x, scale) | (q8c(b.y, scale) << 8) | (q8c(b.z, scale) << 16) | (q8c(b.w, scale) << 24);
    *(int2*)(q + (long long)r * 512 + t * 2) = o2;
    if (t == 0) s[r] = scale;
}

// ---------------- routing: token-major positions via warp ballots (1 block, warp = expert) ----------------
__global__ void k_route() {
    int w = threadIdx.x >> 5, lane = threadIdx.x & 31;
    int base = 0;
    for (int c = 0; c < (T_TOK * K_TOP) / 32; c++) {
        int i = c * 32 + lane;
        int e = g_topk_i[i];
        unsigned mask = __ballot_sync(0xffffffffu, e == w);
        if (e == w) {
            int pos = base + __popc(mask & ((1u << lane) - 1u));
            if (pos < CAP) {
                g_rowsrc[w * CAP + pos] = i >> 2;   // source token
                g_slot[i] = w * CAP + pos;
            } else {
                g_slot[i] = -1;                      // dropped (over capacity)
            }
        }
        base += __popc(mask);
    }
    int cnt = min(base, CAP);
    if (lane == 0) g_cnt[w] = cnt;
    for (int p = cnt + lane; p < CAP; p += 32) g_rowsrc[w * CAP + p] = -1;
}

// ---------------- GEMM1 (int8 dp4a) + dequant + swiglu, fused gate/up pairing ----------------
// grid: (x=32 col-tiles of 64 gate cols, y=8 row-tiles of 64, z=E). BK = 64 int8 (16 int32).
__global__ void __launch_bounds__(256) k_gemm1(const float* __restrict__ w1s,
                                               const float* __restrict__ w1b,
                                               const float* __restrict__ smooth) {
    int e = blockIdx.z, mt = blockIdx.y, nt = blockIdx.x;
    int cnt = g_cnt[e];
    if (mt * 64 >= cnt) return;

    __shared__ int As[64][17];
    __shared__ int Bs[16][132];
    __shared__ int s_src[64];
    __shared__ float s_xs[64];

    int t = threadIdx.x;
    if (t < 64) {
        int s = g_rowsrc[e * CAP + mt * 64 + t];
        s_src[t] = s;
        s_xs[t]  = (s >= 0) ? g_xs[s] : 0.0f;
    }
    __syncthreads();

    int accg[4][4], accu[4][4];
    #pragma unroll
    for (int i = 0; i < 4; i++)
        #pragma unroll
        for (int j = 0; j < 4; j++) { accg[i][j] = 0; accu[i][j] = 0; }

    int ty = t >> 4, tx = t & 15;
    int am = t >> 2, ak = (t & 3) * 4;
    int bk = t >> 4, bc = (t & 15) * 8;
    const long long wbase = (long long)e * (H_DIM / 4) * N1;

    for (int kt = 0; kt < (H_DIM / 4) / 16; ++kt) {
        int src = s_src[am];
        int4 av = make_int4(0, 0, 0, 0);
        if (src >= 0) av = *(const int4*)&g_xq[src * (H_DIM / 4) + kt * 16 + ak];
        As[am][ak] = av.x; As[am][ak + 1] = av.y; As[am][ak + 2] = av.z; As[am][ak + 3] = av.w;

        long long col = (bc < 64) ? (long long)(nt * 64 + bc) : (long long)(I_DIM + nt * 64 + (bc - 64));
        const int* gp = &g_w1p[wbase + (long long)(kt * 16 + bk) * N1 + col];
        int4 b0 = *(const int4*)gp;
        int4 b1 = *(const int4*)(gp + 4);
        *(int4*)&Bs[bk][bc]     = b0;
        *(int4*)&Bs[bk][bc + 4] = b1;
        __syncthreads();

        #pragma unroll
        for (int kk = 0; kk < 16; ++kk) {
            int a[4];
            #pragma unroll
            for (int i = 0; i < 4; i++) a[i] = As[ty * 4 + i][kk];
            int4 bgv = *(const int4*)&Bs[kk][tx * 4];
            int4 buv = *(const int4*)&Bs[kk][64 + tx * 4];
            int bg[4] = {bgv.x, bgv.y, bgv.z, bgv.w};
            int bu[4] = {buv.x, buv.y, buv.z, buv.w};
            #pragma unroll
            for (int i = 0; i < 4; i++)
                #pragma unroll
                for (int j = 0; j < 4; j++) {
                    accg[i][j] = __dp4a(a[i], bg[j], accg[i][j]);
                    accu[i][j] = __dp4a(a[i], bu[j], accu[i][j]);
                }
        }
        __syncthreads();
    }

    // dequant + gpt-oss swiglu + smooth, write act
    #pragma unroll
    for (int i = 0; i < 4; i++) {
        int m = ty * 4 + i;
        float xs = s_xs[m];
        long long rglob = (long long)e * CAP + mt * 64 + m;
        float4 res;
        #pragma unroll
        for (int j = 0; j < 4; j++) {
            int n = nt * 64 + tx * 4 + j;
            float yg = (float)accg[i][j] * xs * w1s[e * N1 + n] + w1b[e * N1 + n];
            float yu = (float)accu[i][j] * xs * w1s[e * N1 + I_DIM + n] + w1b[e * N1 + I_DIM + n];
            float gg = fminf(yg, 7.0f);
            float uu = fminf(fmaxf(yu, -7.0f), 7.0f);
            float act = gg / (1.0f + expf(-1.702f * gg)) * (uu + 1.0f) * smooth[e * I_DIM + n];
            ((float*)&res)[j] = act;
        }
        *(float4*)&g_act[rglob * I_DIM + nt * 64 + tx * 4] = res;
    }
}

// ---------------- GEMM2 (int8 dp4a) + dequant ----------------
// grid: (x=16 col-tiles of 128, y=8 row-tiles of 64, z=E)
__global__ void __launch_bounds__(256) k_gemm2(const float* __restrict__ w2s,
                                               const float* __restrict__ w2b) {
    int e = blockIdx.z, mt = blockIdx.y, nt = blockIdx.x;
    int cnt = g_cnt[e];
    if (mt * 64 >= cnt) return;

    __shared__ int As[64][17];
    __shared__ int Bs[16][132];
    __shared__ float s_hs[64];

    int t = threadIdx.x;
    if (t < 64) s_hs[t] = g_hs[e * CAP + mt * 64 + t];
    __syncthreads();

    int acc[4][8];
    #pragma unroll
    for (int i = 0; i < 4; i++)
        #pragma unroll
        for (int j = 0; j < 8; j++) acc[i][j] = 0;

    int ty = t >> 4, tx = t & 15;
    int am = t >> 2, ak = (t & 3) * 4;
    int bk = t >> 4, bc = (t & 15) * 8;
    const long long wbase = (long long)e * (I_DIM / 4) * H_DIM;

    for (int kt = 0; kt < (I_DIM / 4) / 16; ++kt) {
        long long row = (long long)e * CAP + mt * 64 + am;
        int4 av = *(const int4*)&g_hq[row * (I_DIM / 4) + kt * 16 + ak];
        As[am][ak] = av.x; As[am][ak + 1] = av.y; As[am][ak + 2] = av.z; As[am][ak + 3] = av.w;

        const int* gp = &g_w2p[wbase + (long long)(kt * 16 + bk) * H_DIM + nt * 128 + bc];
        int4 b0 = *(const int4*)gp;
        int4 b1 = *(const int4*)(gp + 4);
        *(int4*)&Bs[bk][bc]     = b0;
        *(int4*)&Bs[bk][bc + 4] = b1;
        __syncthreads();

        #pragma unroll
        for (int kk = 0; kk < 16; ++kk) {
            int a[4];
            #pragma unroll
            for (int i = 0; i < 4; i++) a[i] = As[ty * 4 + i][kk];
            int4 b0v = *(const int4*)&Bs[kk][tx * 8];
            int4 b1v = *(const int4*)&Bs[kk][tx * 8 + 4];
            int b[8] = {b0v.x, b0v.y, b0v.z, b0v.w, b1v.x, b1v.y, b1v.z, b1v.w};
            #pragma unroll
            for (int i = 0; i < 4; i++)
                #pragma unroll
                for (int j = 0; j < 8; j++)
                    acc[i][j] = __dp4a(a[i], b[j], acc[i][j]);
        }
        __syncthreads();
    }

    #pragma unroll
    for (int i = 0; i < 4; i++) {
        int m = ty * 4 + i;
        float hs = s_hs[m];
        long long row = (long long)e * CAP + mt * 64 + m;
        float4 r0, r1;
        #pragma unroll
        for (int j = 0; j < 8; j++) {
            int n = nt * 128 + tx * 8 + j;
            float z = (float)acc[i][j] * hs * w2s[e * H_DIM + n] + w2b[e * H_DIM + n];
            if (j < 4) ((float*)&r0)[j] = z; else ((float*)&r1)[j - 4] = z;
        }
        float* zp = &g_z[row * H_DIM + nt * 128 + tx * 8];
        *(float4*)zp = r0;
        *(float4*)(zp + 4) = r1;
    }
}

// ---------------- combine: out[t] = sum_k w * z[slot] (gather, no atomics) ----------------
__global__ void k_combine(float* __restrict__ out) {
    int tkn = blockIdx.x, t = threadIdx.x;
    int h0 = t * 8;
    float r[8] = {0, 0, 0, 0, 0, 0, 0, 0};
    #pragma unroll
    for (int k = 0; k < K_TOP; k++) {
        int sl = g_slot[tkn * K_TOP + k];
        if (sl >= 0) {
            float w = g_topk_w[tkn * K_TOP + k];
            const float4* zp = (const float4*)&g_z[(long long)sl * H_DIM + h0];
            float4 z0 = zp[0], z1 = zp[1];
            r[0] += w * z0.x; r[1] += w * z0.y; r[2] += w * z0.z; r[3] += w * z0.w;
            r[4] += w * z1.x; r[5] += w * z1.y; r[6] += w * z1.z; r[7] += w * z1.w;
        }
    }
    float4 o0 = make_float4(r[0], r[1], r[2], r[3]);
    float4 o1 = make_float4(r[4], r[5], r[6], r[7]);
    float* op = out + (long long)tkn * H_DIM + h0;
    *(float4*)op = o0;
    *(float4*)(op + 4) = o1;
}

// ---------------- launch ----------------
extern "C" void kernel_launch(void* const* d_in, const int* in_sizes, int n_in,
                              void* d_out, int out_size) {
    const float* hidden = (const float*)d_in[0];
    const float* logits = (const float*)d_in[1];
    const float* w1     = (const float*)d_in[2];
    const float* w1s    = (const float*)d_in[3];
    const float* w1b    = (const float*)d_in[4];
    const float* smooth = (const float*)d_in[5];
    const float* w2     = (const float*)d_in[6];
    const float* w2s    = (const float*)d_in[7];
    const float* w2b    = (const float*)d_in[8];
    float* out = (float*)d_out;

    // repack weights to K-packed int8 (done every launch; deterministic)
    k_pack<<<32768, 256>>>(w1, 0, H_DIM, N1);
    k_pack<<<16384, 256>>>(w2, 1, I_DIM, H_DIM);

    // gating + token quant + routing
    k_gate<<<T_TOK, 32>>>(logits);
    k_quant<<<T_TOK, 256>>>(hidden, 0);
    k_route<<<1, 512>>>();

    // expert MLP
    k_gemm1<<<dim3(32, 8, E_EXP), 256>>>(w1s, w1b, smooth);
    k_quant<<<E_EXP * CAP, 256>>>(nullptr, 1);
    k_gemm2<<<dim3(16, 8, E_EXP), 256>>>(w2s, w2b);

    // weighted combine
    k_combine<<<T_TOK, 256>>>(out);
}